// round 13
// baseline (speedup 1.0000x reference)
#include <cuda_runtime.h>
#include <cstdint>

// GlobalNHC: Nose-Hoover chain thermostat, B=32, N=131072, D=3, C=5, NRESPA=2 x 7 SY.
// Persistent kernel, 128 blocks x 1024 threads (1 CTA/SM).
// Phase 1 (wavefront-optimized): mom cp.async'd coalesced into smem in two
// 12-float4 chunks; KE computed from smem in QUAD layout (3 consecutive float4s
// = 4 atoms per step; 48B lane stride is bank-conflict-free for LDS.128), with
// mas fetched as coalesced float4 (1 LDG.128 per 4 atoms, prefetched).
// Chunk B stays in smem for phase 3. Per-batch sync; chain on thread 0 (MUFU ex2);
// phase 3: chunk B from smem + chunk A from L2-hot global, streaming stores.
//
// mom enters the integrator only via KE = sum(mom^2/mas) and a uniform per-batch
// rescale, so the 14 substeps collapse to scalar chain math with KE *= s^2.

#define BB     32
#define NATM   131072
#define DDIM   3
#define CCH    5
#define NPER   (NATM * DDIM)        // 393216 floats per batch
#define NVEC   (NPER / 4)           // 98304 float4 per batch
#define GX     4                    // blocks per batch
#define NBLK   (GX * BB)            // 128 blocks total (1 CTA/SM)
#define TPB    1024
#define V4PB   (NVEC / GX)          // 24576 float4 per block
#define CHUNK  12                   // float4s per thread per chunk (2 chunks)
#define QPC    (CHUNK * TPB / 3)    // 4096 quads (4 atoms) per chunk
#define QPT    (QPC / TPB)          // 4 quads per thread per chunk
#define ATPB   (V4PB * 4 / 3)       // 32768 atoms per block
#define SMEM_DYN (CHUNK * TPB * 16) // 196608 B
#define NRESPA_ 2
#define LOG2E  1.4426950408889634f

__device__ double       g_part[NBLK];            // per-block KE partials
__device__ unsigned int g_barb[BB * 32];         // per-batch counters (128B apart)

__device__ __forceinline__ void st_stream(float4* p, float4 v) {
    asm volatile("st.global.cs.v4.f32 [%0], {%1,%2,%3,%4};"
                 :: "l"(p), "f"(v.x), "f"(v.y), "f"(v.z), "f"(v.w) : "memory");
}

__device__ __forceinline__ float ex2_approx(float x) {   // 2^x via MUFU.EX2
    float r;
    asm("ex2.approx.f32 %0, %1;" : "=f"(r) : "f"(x));
    return r;
}

__device__ __forceinline__ uint32_t smem_u32(const void* p) {
    uint32_t a;
    asm("{ .reg .u64 t; cvta.to.shared.u64 t, %1; cvt.u32.u64 %0, t; }"
        : "=r"(a) : "l"(p));
    return a;
}

// KE of one atom-quad: 3 float4s (12 elements) + float4 of masses
__device__ __forceinline__ float quad_ke(float4 v0, float4 v1, float4 v2,
                                         float4 ms) {
    float s0 = v0.x * v0.x + v0.y * v0.y + v0.z * v0.z;
    float s1 = v0.w * v0.w + v1.x * v1.x + v1.y * v1.y;
    float s2 = v1.z * v1.z + v1.w * v1.w + v2.x * v2.x;
    float s3 = v2.y * v2.y + v2.z * v2.z + v2.w * v2.w;
    return __fdividef(s0, ms.x) + __fdividef(s1, ms.y)
         + __fdividef(s2, ms.z) + __fdividef(s3, ms.w);
}

__global__ void __launch_bounds__(TPB, 1)
nhc_fused_kernel(const float4* __restrict__ mom4,
                 const float4* __restrict__ mas4,
                 const float*  __restrict__ kbt,
                 const float*  __restrict__ dtm,
                 const float*  __restrict__ pos_nhc,
                 const float*  __restrict__ mom_nhc,
                 const float*  __restrict__ mas_nhc,
                 const float*  __restrict__ stp_p,
                 float4* __restrict__ out_mom4,
                 float*  __restrict__ out_posnhc,
                 float*  __restrict__ out_momnhc) {
    extern __shared__ float4 s_stage[];        // CHUNK * TPB float4s
    const int gx = blockIdx.x;                 // 0..GX-1
    const int b  = blockIdx.y;                 // batch
    const int t  = threadIdx.x;

    const float4* m  = mom4 + (size_t)b * NVEC;
    const float4* ma = mas4 + (size_t)b * (NATM / 4);
    const int vbase = gx * V4PB;               // float4 base in batch
    const int qbase = gx * (ATPB / 4);         // quad (mas4) base in batch

    const uint32_t sbase = smem_u32(s_stage);
    float acc = 0.0f;

    // =============== Phase 1, chunk A (k = 0..11) ===========================
    #pragma unroll
    for (int k = 0; k < CHUNK; k++) {
        const uint32_t saddr = sbase + (uint32_t)(k * TPB + t) * 16u;
        const float4* gaddr = &m[vbase + k * TPB + t];
        asm volatile("cp.async.cg.shared.global [%0], [%1], 16;"
                     :: "r"(saddr), "l"(gaddr) : "memory");
    }
    asm volatile("cp.async.commit_group;" ::: "memory");

    float4 msA[QPT];                           // coalesced mas prefetch (chunk A)
    #pragma unroll
    for (int i = 0; i < QPT; i++)
        msA[i] = ma[qbase + i * TPB + t];

    asm volatile("cp.async.wait_group 0;" ::: "memory");
    __syncthreads();

    #pragma unroll
    for (int i = 0; i < QPT; i++) {
        const int q = i * TPB + t;             // local quad in chunk
        float4 v0 = s_stage[3 * q + 0];
        float4 v1 = s_stage[3 * q + 1];
        float4 v2 = s_stage[3 * q + 2];
        acc += quad_ke(v0, v1, v2, msA[i]);
    }
    __syncthreads();                            // protect smem before overwrite

    // =============== Phase 1, chunk B (k = 12..23) — stays for phase 3 ======
    #pragma unroll
    for (int k = 0; k < CHUNK; k++) {
        const uint32_t saddr = sbase + (uint32_t)(k * TPB + t) * 16u;
        const float4* gaddr = &m[vbase + (CHUNK + k) * TPB + t];
        asm volatile("cp.async.cg.shared.global [%0], [%1], 16;"
                     :: "r"(saddr), "l"(gaddr) : "memory");
    }
    asm volatile("cp.async.commit_group;" ::: "memory");

    float4 msB[QPT];
    #pragma unroll
    for (int i = 0; i < QPT; i++)
        msB[i] = ma[qbase + QPC + i * TPB + t];

    asm volatile("cp.async.wait_group 0;" ::: "memory");
    __syncthreads();

    #pragma unroll
    for (int i = 0; i < QPT; i++) {
        const int q = i * TPB + t;
        float4 v0 = s_stage[3 * q + 0];
        float4 v1 = s_stage[3 * q + 1];
        float4 v2 = s_stage[3 * q + 2];
        acc += quad_ke(v0, v1, v2, msB[i]);
    }

    // ---------------- block reduction -------------------------------------
    #pragma unroll
    for (int off = 16; off > 0; off >>= 1)
        acc += __shfl_down_sync(0xffffffffu, acc, off);

    __shared__ double s_warp[TPB / 32];
    __shared__ float  s_scale;
    const int wid = t >> 5, lid = t & 31;
    if (lid == 0) s_warp[wid] = (double)acc;
    __syncthreads();

    if (t == 0) {
        double tot = 0.0;
        #pragma unroll
        for (int i = 0; i < TPB / 32; i++) tot += s_warp[i];
        g_part[b * GX + gx] = tot;
        __threadfence();

        // -------- Per-batch sync: this batch's GX blocks (replay-safe) -----
        unsigned int* bar = &g_barb[b * 32];
        unsigned int ticket = atomicAdd(bar, 1u);
        unsigned int target = (ticket / GX + 1u) * GX;
        while (*((volatile unsigned int*)bar) < target) __nanosleep(32);
        __threadfence();

        // ---------------- Phase 2: chain math for batch b ----------------
        double ked = 0.0;
        #pragma unroll
        for (int i = 0; i < GX; i++) ked += g_part[b * GX + i];

        const float wts[7] = {
            0.78451361047756f, 0.235573213359357f, -1.17767998417887f,
            (float)(1.0 - 2.0 * (0.78451361047756 + 0.235573213359357 - 1.17767998417887)),
            -1.17767998417887f, 0.235573213359357f, 0.78451361047756f
        };

        const double kgd = (double)kbt[b] * (double)(NATM * DDIM);
        const float  kbT = kbt[b];
        const float  dts = dtm[b] * (stp_p[0] / (float)NRESPA_);

        float pn[CCH], mn[CCH], imq[CCH];
        #pragma unroll
        for (int c = 0; c < CCH; c++) {
            pn[c]  = pos_nhc[b * CCH + c];
            mn[c]  = mom_nhc[b * CCH + c];
            imq[c] = 1.0f / mas_nhc[b * CCH + c];
        }

        double cum = 1.0;
        for (int r = 0; r < NRESPA_; r++) {
            #pragma unroll
            for (int iw = 0; iw < 7; iw++) {
                const float dea   = dts * wts[iw];
                const float dea2  = dea * 0.5f;
                const float dea4L = dea * (0.25f * LOG2E);
                const float deaL  = dea * LOG2E;

                float g[CCH], mc[CCH];
                g[0] = (float)(ked - kgd);
                #pragma unroll
                for (int j = 1; j < CCH; j++)
                    g[j] = mn[j - 1] * mn[j - 1] * imq[j - 1] - kbT;

                #pragma unroll
                for (int c = 0; c < CCH; c++) mc[c] = mn[c];
                mc[CCH - 1] += g[CCH - 1] * dea2;

                #pragma unroll
                for (int j = CCH - 2; j >= 0; j--) {
                    float f = ex2_approx(-mc[j + 1] * imq[j + 1] * dea4L);
                    mc[j] = (mc[j] * f + g[j] * dea2) * f;
                }

                #pragma unroll
                for (int c = 0; c < CCH; c++) pn[c] += mc[c] * imq[c] * dea;

                const float s = ex2_approx(-mc[0] * imq[0] * deaL);
                cum *= (double)s;
                ked *= (double)s * (double)s;

                g[0] = (float)(ked - kgd);
                #pragma unroll
                for (int j = CCH - 2; j >= 0; j--) {
                    float f = ex2_approx(-mc[j + 1] * imq[j + 1] * dea4L);
                    mc[j] = (mc[j] * f + g[j] * dea2) * f;
                }
                mc[CCH - 1] += g[CCH - 1] * dea2;

                #pragma unroll
                for (int c = 0; c < CCH; c++) mn[c] = mc[c];
            }
        }

        s_scale = (float)cum;
        if (gx == 0) {
            #pragma unroll
            for (int c = 0; c < CCH; c++) {
                out_posnhc[b * CCH + c] = pn[c];
                out_momnhc[b * CCH + c] = mn[c];
            }
        }
    }
    __syncthreads();

    // ------- Phase 3: rescale. Chunk B from smem, chunk A from L2-hot ------
    const float s = s_scale;
    float4* o = out_mom4 + (size_t)b * NVEC;
    #pragma unroll 4
    for (int k = 0; k < CHUNK; k++) {          // chunk B (smem resident)
        float4 v = s_stage[k * TPB + t];
        v.x *= s; v.y *= s; v.z *= s; v.w *= s;
        st_stream(o + vbase + (CHUNK + k) * TPB + t, v);
    }
    #pragma unroll 4
    for (int k = 0; k < CHUNK; k++) {          // chunk A (global, L2-hot)
        const int L = vbase + k * TPB + t;
        float4 v = m[L];
        v.x *= s; v.y *= s; v.z *= s; v.w *= s;
        st_stream(o + L, v);
    }
}

// ---------------------------------------------------------------------------
extern "C" void kernel_launch(void* const* d_in, const int* in_sizes, int n_in,
                              void* d_out, int out_size) {
    // inputs: 0 pos, 1 mom, 2 mas, 3 kbt, 4 dtm, 5 pos_nhc, 6 mom_nhc, 7 mas_nhc, 8 stp
    const float* mom     = (const float*)d_in[1];
    const float* mas     = (const float*)d_in[2];
    const float* kbt     = (const float*)d_in[3];
    const float* dtm     = (const float*)d_in[4];
    const float* pos_nhc = (const float*)d_in[5];
    const float* mom_nhc = (const float*)d_in[6];
    const float* mas_nhc = (const float*)d_in[7];
    const float* stp     = (const float*)d_in[8];

    float* out = (float*)d_out;
    float* out_mom    = out;                          // [B, N, D]
    float* out_posnhc = out + (size_t)BB * NPER;      // [B, C]
    float* out_momnhc = out_posnhc + BB * CCH;        // [B, C]

    static int attr_done = 0;
    if (!attr_done) {
        cudaFuncSetAttribute(nhc_fused_kernel,
                             cudaFuncAttributeMaxDynamicSharedMemorySize,
                             SMEM_DYN);
        attr_done = 1;
    }

    dim3 grid(GX, BB);                                // 128 blocks, 1 per SM
    nhc_fused_kernel<<<grid, TPB, SMEM_DYN>>>(
        (const float4*)mom, (const float4*)mas,
        kbt, dtm, pos_nhc, mom_nhc, mas_nhc, stp,
        (float4*)out_mom, out_posnhc, out_momnhc);
}

// round 14
// speedup vs baseline: 1.1403x; 1.1403x over previous
#include <cuda_runtime.h>
#include <cstdint>

// GlobalNHC: Nose-Hoover chain thermostat, B=32, N=131072, D=3, C=5, NRESPA=2 x 7 SY.
// Persistent kernel, 128 blocks x 1024 threads (1 CTA/SM). R10 base with a
// WARP-DECOUPLED epilogue: no block barrier between KE reduction and rescale.
// Warps publish partials, thread 0 alone syncs across blocks + runs the chain;
// meanwhile every other warp prefetches phase-3 loads and spins on a volatile
// flag only right before the first multiply.
//
// mom enters the integrator only via KE = sum(mom^2/mas) and a uniform per-batch
// rescale, so the 14 substeps collapse to scalar chain math with KE *= s^2.

#define BB     32
#define NATM   131072
#define DDIM   3
#define CCH    5
#define NPER   (NATM * DDIM)        // 393216 floats per batch
#define NVEC   (NPER / 4)           // 98304 float4 per batch
#define GX     4                    // blocks per batch
#define NBLK   (GX * BB)            // 128 blocks total (1 CTA/SM)
#define TPB    1024
#define V4PB   (NVEC / GX)          // 24576 float4 per block
#define V4PT   (V4PB / TPB)         // 24 float4 per thread
#define SSTG   12                   // float4s per thread staged in smem
#define SMEM_DYN (SSTG * TPB * 16)  // 196608 B
#define NRESPA_ 2
#define LOG2E  1.4426950408889634f

__device__ double       g_part[NBLK];            // per-block KE partials
__device__ unsigned int g_barb[BB * 32];         // per-batch counters (128B apart)

__device__ __forceinline__ void st_stream(float4* p, float4 v) {
    asm volatile("st.global.cs.v4.f32 [%0], {%1,%2,%3,%4};"
                 :: "l"(p), "f"(v.x), "f"(v.y), "f"(v.z), "f"(v.w) : "memory");
}

__device__ __forceinline__ float ex2_approx(float x) {   // 2^x via MUFU.EX2
    float r;
    asm("ex2.approx.f32 %0, %1;" : "=f"(r) : "f"(x));
    return r;
}

__global__ void __launch_bounds__(TPB, 1)
nhc_fused_kernel(const float4* __restrict__ mom4,
                 const float*  __restrict__ mas,
                 const float*  __restrict__ kbt,
                 const float*  __restrict__ dtm,
                 const float*  __restrict__ pos_nhc,
                 const float*  __restrict__ mom_nhc,
                 const float*  __restrict__ mas_nhc,
                 const float*  __restrict__ stp_p,
                 float4* __restrict__ out_mom4,
                 float*  __restrict__ out_posnhc,
                 float*  __restrict__ out_momnhc) {
    extern __shared__ float4 s_stage[];        // SSTG * TPB float4s
    __shared__ double        s_warp[TPB / 32];
    __shared__ volatile int  s_cnt;            // warps-arrived counter
    __shared__ volatile int  s_flag;           // scale-ready flag
    __shared__ volatile float s_scale_v;

    const int gx = blockIdx.x;                 // 0..GX-1
    const int b  = blockIdx.y;                 // batch
    const int t  = threadIdx.x;
    const int wid = t >> 5, lid = t & 31;

    if (t == 0) { s_cnt = 0; s_flag = 0; }
    __syncthreads();                           // only block-wide barrier

    const float4* m    = mom4 + (size_t)b * NVEC;
    const float*  masb = mas  + (size_t)b * NATM;
    const int vbase = gx * V4PB;

    // ---------------- Phase 1: KE partial, fully coalesced ----------------
    // float4 at index L covers elements E=4L..4L+3; atom a = E/3, r = E%3 splits
    // the 4 squares between atoms a and a+1.
    float acc = 0.0f;
    #pragma unroll 4
    for (int k = 0; k < SSTG; k++) {           // staged half: also STS to smem
        const int L = vbase + k * TPB + t;
        float4 v = m[L];
        s_stage[k * TPB + t] = v;
        const unsigned E = 4u * (unsigned)L;
        const unsigned a = __umulhi(E, 0xAAAAAAABu) >> 1;   // E/3
        const unsigned r = E - 3u * a;                      // E%3
        float p  = v.x * v.x, q  = v.y * v.y;
        float u  = v.z * v.z, w2 = v.w * v.w;
        float cA = p, cB = w2;
        if (r < 2u)  cA += q; else cB += q;
        if (r == 0u) cA += u; else cB += u;
        acc += __fdividef(cA, masb[a]) + __fdividef(cB, masb[a + 1]);
    }
    #pragma unroll 4
    for (int k = SSTG; k < V4PT; k++) {        // plain half
        const int L = vbase + k * TPB + t;
        float4 v = m[L];
        const unsigned E = 4u * (unsigned)L;
        const unsigned a = __umulhi(E, 0xAAAAAAABu) >> 1;
        const unsigned r = E - 3u * a;
        float p  = v.x * v.x, q  = v.y * v.y;
        float u  = v.z * v.z, w2 = v.w * v.w;
        float cA = p, cB = w2;
        if (r < 2u)  cA += q; else cB += q;
        if (r == 0u) cA += u; else cB += u;
        acc += __fdividef(cA, masb[a]) + __fdividef(cB, masb[a + 1]);
    }

    // warp reduce (float); lane 0 publishes and bumps the counter
    #pragma unroll
    for (int off = 16; off > 0; off >>= 1)
        acc += __shfl_down_sync(0xffffffffu, acc, off);
    if (lid == 0) {
        s_warp[wid] = (double)acc;
        __threadfence_block();
        atomicAdd((int*)&s_cnt, 1);
    }

    // ---- Thread 0 alone: gather, inter-block sync, chain, publish scale ---
    if (t == 0) {
        while (s_cnt < TPB / 32) __nanosleep(20);
        __threadfence_block();
        double tot = 0.0;
        #pragma unroll
        for (int i = 0; i < TPB / 32; i++) tot += s_warp[i];
        g_part[b * GX + gx] = tot;
        __threadfence();

        unsigned int* bar = &g_barb[b * 32];
        unsigned int ticket = atomicAdd(bar, 1u);
        unsigned int target = (ticket / GX + 1u) * GX;
        while (*((volatile unsigned int*)bar) < target) __nanosleep(32);
        __threadfence();

        double ked = 0.0;
        #pragma unroll
        for (int i = 0; i < GX; i++) ked += g_part[b * GX + i];

        const float wts[7] = {
            0.78451361047756f, 0.235573213359357f, -1.17767998417887f,
            (float)(1.0 - 2.0 * (0.78451361047756 + 0.235573213359357 - 1.17767998417887)),
            -1.17767998417887f, 0.235573213359357f, 0.78451361047756f
        };

        const double kgd = (double)kbt[b] * (double)(NATM * DDIM);
        const float  kbT = kbt[b];
        const float  dts = dtm[b] * (stp_p[0] / (float)NRESPA_);

        float pn[CCH], mn[CCH], imq[CCH];
        #pragma unroll
        for (int c = 0; c < CCH; c++) {
            pn[c]  = pos_nhc[b * CCH + c];
            mn[c]  = mom_nhc[b * CCH + c];
            imq[c] = 1.0f / mas_nhc[b * CCH + c];
        }

        double cum = 1.0;
        for (int r = 0; r < NRESPA_; r++) {
            #pragma unroll
            for (int iw = 0; iw < 7; iw++) {
                const float dea   = dts * wts[iw];
                const float dea2  = dea * 0.5f;
                const float dea4L = dea * (0.25f * LOG2E);
                const float deaL  = dea * LOG2E;

                float g[CCH], mc[CCH];
                g[0] = (float)(ked - kgd);
                #pragma unroll
                for (int j = 1; j < CCH; j++)
                    g[j] = mn[j - 1] * mn[j - 1] * imq[j - 1] - kbT;

                #pragma unroll
                for (int c = 0; c < CCH; c++) mc[c] = mn[c];
                mc[CCH - 1] += g[CCH - 1] * dea2;

                #pragma unroll
                for (int j = CCH - 2; j >= 0; j--) {
                    float f = ex2_approx(-mc[j + 1] * imq[j + 1] * dea4L);
                    mc[j] = (mc[j] * f + g[j] * dea2) * f;
                }

                #pragma unroll
                for (int c = 0; c < CCH; c++) pn[c] += mc[c] * imq[c] * dea;

                const float s = ex2_approx(-mc[0] * imq[0] * deaL);
                cum *= (double)s;
                ked *= (double)s * (double)s;

                g[0] = (float)(ked - kgd);
                #pragma unroll
                for (int j = CCH - 2; j >= 0; j--) {
                    float f = ex2_approx(-mc[j + 1] * imq[j + 1] * dea4L);
                    mc[j] = (mc[j] * f + g[j] * dea2) * f;
                }
                mc[CCH - 1] += g[CCH - 1] * dea2;

                #pragma unroll
                for (int c = 0; c < CCH; c++) mn[c] = mc[c];
            }
        }

        if (gx == 0) {
            #pragma unroll
            for (int c = 0; c < CCH; c++) {
                out_posnhc[b * CCH + c] = pn[c];
                out_momnhc[b * CCH + c] = mn[c];
            }
        }

        s_scale_v = (float)cum;
        __threadfence_block();
        s_flag = 1;
    }

    // ------- Phase 3 (NO barrier): prefetch loads, then spin for scale -----
    float4* o = out_mom4 + (size_t)b * NVEC;

    // prefetch first 4 of the global half while thread 0 syncs/chains
    float4 pre[4];
    #pragma unroll
    for (int j = 0; j < 4; j++)
        pre[j] = m[vbase + (SSTG + j) * TPB + t];

    if (s_flag == 0) {
        while (s_flag == 0) __nanosleep(20);
    }
    __threadfence_block();
    const float s = s_scale_v;

    // staged half from smem (own slots; written by this thread in phase 1)
    #pragma unroll 4
    for (int k = 0; k < SSTG; k++) {
        float4 v = s_stage[k * TPB + t];
        v.x *= s; v.y *= s; v.z *= s; v.w *= s;
        st_stream(o + vbase + k * TPB + t, v);
    }
    // prefetched 4
    #pragma unroll
    for (int j = 0; j < 4; j++) {
        float4 v = pre[j];
        v.x *= s; v.y *= s; v.z *= s; v.w *= s;
        st_stream(o + vbase + (SSTG + j) * TPB + t, v);
    }
    // remaining 8 of the global half (L2-hot)
    #pragma unroll 4
    for (int k = SSTG + 4; k < V4PT; k++) {
        const int L = vbase + k * TPB + t;
        float4 v = m[L];
        v.x *= s; v.y *= s; v.z *= s; v.w *= s;
        st_stream(o + L, v);
    }
}

// ---------------------------------------------------------------------------
extern "C" void kernel_launch(void* const* d_in, const int* in_sizes, int n_in,
                              void* d_out, int out_size) {
    // inputs: 0 pos, 1 mom, 2 mas, 3 kbt, 4 dtm, 5 pos_nhc, 6 mom_nhc, 7 mas_nhc, 8 stp
    const float* mom     = (const float*)d_in[1];
    const float* mas     = (const float*)d_in[2];
    const float* kbt     = (const float*)d_in[3];
    const float* dtm     = (const float*)d_in[4];
    const float* pos_nhc = (const float*)d_in[5];
    const float* mom_nhc = (const float*)d_in[6];
    const float* mas_nhc = (const float*)d_in[7];
    const float* stp     = (const float*)d_in[8];

    float* out = (float*)d_out;
    float* out_mom    = out;                          // [B, N, D]
    float* out_posnhc = out + (size_t)BB * NPER;      // [B, C]
    float* out_momnhc = out_posnhc + BB * CCH;        // [B, C]

    static int attr_done = 0;
    if (!attr_done) {
        cudaFuncSetAttribute(nhc_fused_kernel,
                             cudaFuncAttributeMaxDynamicSharedMemorySize,
                             SMEM_DYN);
        attr_done = 1;
    }

    dim3 grid(GX, BB);                                // 128 blocks, 1 per SM
    nhc_fused_kernel<<<grid, TPB, SMEM_DYN>>>(
        (const float4*)mom, mas,
        kbt, dtm, pos_nhc, mom_nhc, mas_nhc, stp,
        (float4*)out_mom, out_posnhc, out_momnhc);
}